// round 4
// baseline (speedup 1.0000x reference)
#include <cuda_runtime.h>

#define NN 1024
#define BB 128
#define TS 32
#define NT (NN/TS)        // 32
#define NTILES 528        // upper-triangular 32x32 tiles

// Partials [batch][tile] so the final reduce streams contiguous rows.
__device__ float g_qpart[BB][NTILES];
__device__ unsigned int g_done = 0;

typedef unsigned long long u64;

__device__ __forceinline__ u64 fma2(u64 a, u64 b, u64 c) {
    u64 d;
    asm("fma.rn.f32x2 %0, %1, %2, %3;" : "=l"(d) : "l"(a), "l"(b), "l"(c));
    return d;
}
__device__ __forceinline__ u64 pack2(float lo, float hi) {
    u64 d; asm("mov.b64 %0, {%1, %2};" : "=l"(d) : "f"(lo), "f"(hi)); return d;
}
__device__ __forceinline__ float sum2(u64 a) {
    float lo, hi; asm("mov.b64 {%0, %1}, %2;" : "=f"(lo), "=f"(hi) : "l"(a));
    return lo + hi;
}

__global__ __launch_bounds__(128, 4)
void potts_fused(const float* __restrict__ vec,
                 const float* __restrict__ W,
                 float* __restrict__ out)
{
    __shared__ __align__(16) float Wt[TS][TS];       // broadcast reads: no pad needed
    __shared__ float Vi[TS][BB + 1];                  // [i][b], padded vs 32-way store conflict
    __shared__ float Vj[TS][BB + 1];
    __shared__ __align__(16) float rs[TS];            // masked row sums
    __shared__ __align__(16) float cs[TS];            // masked col sums
    __shared__ unsigned int s_rank;

    const int tid = threadIdx.x;

    // ---- compact triangular mapping: block t -> (ti, tj), ti <= tj ----
    const int u = (NTILES - 1) - (int)blockIdx.x;
    int r = (int)((sqrtf(8.0f * (float)u + 1.0f) - 1.0f) * 0.5f);
    while ((r + 1) * (r + 2) / 2 <= u) ++r;
    while (r * (r + 1) / 2 > u) --r;
    const int ti = NT - 1 - r;
    const int tj = NT - 1 - (u - r * (r + 1) / 2);
    const int i0 = ti * TS, j0 = tj * TS;
    const bool diag = (ti == tj);

    // ---- stage W tile (triu-masked on diagonal tiles) ----
    #pragma unroll
    for (int idx = tid; idx < TS * TS; idx += 128) {
        int rr = idx >> 5, c = idx & 31;
        float w = W[(i0 + rr) * NN + j0 + c];
        if (diag && c < rr) w = 0.0f;
        Wt[rr][c] = w;
    }
    // ---- stage vector tiles transposed [pos][batch] (gmem-coalesced) ----
    #pragma unroll
    for (int idx = tid; idx < BB * TS; idx += 128) {
        int b = idx >> 5, c = idx & 31;
        Vi[c][b] = vec[b * NN + i0 + c];
        Vj[c][b] = vec[b * NN + j0 + c];
    }
    __syncthreads();

    // ---- batch-independent masked row/col sums ----
    if (tid < TS) {
        float s = 0.0f;
        #pragma unroll
        for (int j = 0; j < TS; j++) s += Wt[tid][j];
        rs[tid] = s;
    } else if (tid < 2 * TS) {
        int j = tid - TS; float s = 0.0f;
        #pragma unroll
        for (int i = 0; i < TS; i++) s += Wt[i][j];
        cs[j] = s;
    }
    __syncthreads();

    // ---- per-batch compute: thread b owns batch b ----
    const int b = tid;

    u64 vj2[TS / 2];
    #pragma unroll
    for (int k = 0; k < TS / 2; k++)
        vj2[k] = pack2(Vj[2 * k][b], Vj[2 * k + 1][b]);

    // lj = sum_j cs[j] * v[b, j]   (packed)
    const u64* cs2 = (const u64*)cs;
    u64 lj2 = 0ull;
    #pragma unroll
    for (int k = 0; k < TS / 2; k++) lj2 = fma2(cs2[k], vj2[k], lj2);
    const float lj = sum2(lj2);

    // bilinear q = v_i^T Wm v_j ; folded linear: accl = sum_i rs[i]*(1 - v_i)
    u64 q2 = 0ull;
    float accl = 0.0f;
    #pragma unroll 8
    for (int i = 0; i < TS; i++) {
        const u64* wrow = (const u64*)Wt[i];          // LDS.64 broadcasts
        u64 in2 = 0ull;
        #pragma unroll
        for (int k = 0; k < TS / 2; k++) in2 = fma2(wrow[k], vj2[k], in2);
        float vi = Vi[i][b];
        q2 = fma2(pack2(vi, vi), in2, q2);
        accl += rs[i] * (1.0f - vi);
    }
    const float res = accl - lj + 2.0f * sum2(q2);

    g_qpart[b][blockIdx.x] = res;

    // ---- last-block fused reduction (deterministic; counter self-resets) ----
    __threadfence();
    __syncthreads();
    if (tid == 0) s_rank = atomicAdd(&g_done, 1u);
    __syncthreads();
    if (s_rank == NTILES - 1) {
        __threadfence();                               // acquire partials
        float s = 0.0f;
        const float4* p = (const float4*)(&g_qpart[b][0]);
        #pragma unroll 4
        for (int k = 0; k < NTILES / 4; k++) {
            float4 v = p[k];
            s += v.x + v.y + v.z + v.w;
        }
        out[b] = s;
        if (tid == 0) g_done = 0;                      // reset for next replay
    }
}

extern "C" void kernel_launch(void* const* d_in, const int* in_sizes, int n_in,
                              void* d_out, int out_size)
{
    const float* vec = (const float*)d_in[0];   // vector        [128, 1024]
    const float* W   = (const float*)d_in[1];   // interactions  [1024, 1024]
    float* out = (float*)d_out;                 // [128]

    potts_fused<<<NTILES, 128>>>(vec, W, out);
}